// round 14
// baseline (speedup 1.0000x reference)
#include <cuda_runtime.h>

#define TSEQ 512
#define INF  14

typedef unsigned long long ull;

__device__ __forceinline__ ull pk(float lo, float hi){
    ull r; asm("mov.b64 %0, {%1,%2};" : "=l"(r) : "f"(lo), "f"(hi)); return r;
}
__device__ __forceinline__ float2 upk(ull v){
    float2 r; asm("mov.b64 {%0,%1}, %2;" : "=f"(r.x), "=f"(r.y) : "l"(v)); return r;
}
__device__ __forceinline__ ull ffma2(ull a, ull b, ull c){
    ull d; asm("fma.rn.f32x2 %0, %1, %2, %3;" : "=l"(d) : "l"(a), "l"(b), "l"(c)); return d;
}
__device__ __forceinline__ float tanhx(float x){
    float r; asm("tanh.approx.f32 %0, %1;" : "=f"(r) : "f"(x)); return r;
}

// 2 batch elements per warp, 16 lanes each: lane = eh*16 + p*8 + j.
// GATE-SPLIT: p=0 lanes own gate rows {i(j), f(j)}, p=1 lanes own {g(j), o(j)}.
// FFMA2 per warp-step = 38 = mathematical minimum for 2 elements.
// Uniform stream: per-lane activation constants (ca,cb) make gate0 a sigmoid
// on p=0 and a tanh on p=1 with the SAME instructions (weights pre-scaled by
// 0.5 for sigmoid gates). Activated gates exchanged via 2x shfl.xor(8)/layer;
// both halves then compute c,h bitwise-identically (2 SEL/layer).
// Depth-2 x prefetch keeps the LDG stream off the recurrence critical path.
__global__ __launch_bounds__(32, 13) void lstm_forex_kernel(
    const float* __restrict__ x,
    const float* __restrict__ Wih1, const float* __restrict__ Whh1,
    const float* __restrict__ bih1, const float* __restrict__ bhh1,
    const float* __restrict__ Wih2, const float* __restrict__ Whh2,
    const float* __restrict__ bih2, const float* __restrict__ bhh2,
    const float* __restrict__ bn_gamma, const float* __restrict__ bn_beta,
    const float* __restrict__ bn_mean, const float* __restrict__ bn_var,
    const float* __restrict__ w1, const float* __restrict__ b1,
    const float* __restrict__ w2, const float* __restrict__ b2,
    float* __restrict__ out, int Bn)
{
    const int lane = threadIdx.x & 31;
    const int j    = lane & 7;
    const int p    = (lane >> 3) & 1;     // 0: gates i,f ; 1: gates g,o
    const int ob   = lane & 24;           // own 8-lane half base
    const int e    = blockIdx.x * 2 + (lane >> 4);
    const bool valid = (e < Bn);
    const int ec = valid ? e : (Bn > 0 ? Bn - 1 : 0);
    const bool isP1 = (p == 1);
    const unsigned FULL = 0xffffffffu;

    // my two gate rows: r0 = i(j) or g(j); r1 = f(j) or o(j)
    const int r0 = p * 16 + j;
    const int r1 = p * 16 + 8 + j;
    // prescale: sigmoid rows by 0.5 (sig(x)=0.5*tanh(0.5x)+0.5), tanh row by 1
    const float s0 = isP1 ? 1.0f : 0.5f;   // gate0: g on p=1 (tanh), i on p=0 (sig)
    const float s1 = 0.5f;                 // gate1: f / o, always sigmoid
    // activation consts for gate0: value = ca*tanhx(acc) + cb
    const float ca = isP1 ? 1.0f : 0.5f;
    const float cb = isP1 ? 0.0f : 0.5f;

    // ---- packed per-lane weights (k-pair packing) ----
    ull wx0[7], wx1[7], wh10[4], wh11[4], wi20[4], wi21[4], wh20[4], wh21[4];
#pragma unroll
    for (int k = 0; k < 7; k++){
        wx0[k] = pk(s0 * Wih1[r0*14 + 2*k], s0 * Wih1[r0*14 + 2*k + 1]);
        wx1[k] = pk(s1 * Wih1[r1*14 + 2*k], s1 * Wih1[r1*14 + 2*k + 1]);
    }
#pragma unroll
    for (int k = 0; k < 4; k++){
        wh10[k] = pk(s0 * Whh1[r0*8 + 2*k], s0 * Whh1[r0*8 + 2*k + 1]);
        wh11[k] = pk(s1 * Whh1[r1*8 + 2*k], s1 * Whh1[r1*8 + 2*k + 1]);
        wi20[k] = pk(s0 * Wih2[r0*8 + 2*k], s0 * Wih2[r0*8 + 2*k + 1]);
        wi21[k] = pk(s1 * Wih2[r1*8 + 2*k], s1 * Wih2[r1*8 + 2*k + 1]);
        wh20[k] = pk(s0 * Whh2[r0*8 + 2*k], s0 * Whh2[r0*8 + 2*k + 1]);
        wh21[k] = pk(s1 * Whh2[r1*8 + 2*k], s1 * Whh2[r1*8 + 2*k + 1]);
    }
    const ull pb10 = pk(s0 * (bih1[r0] + bhh1[r0]), 0.f);
    const ull pb11 = pk(s1 * (bih1[r1] + bhh1[r1]), 0.f);
    const ull pb20 = pk(s0 * (bih2[r0] + bhh2[r0]), 0.f);
    const ull pb21 = pk(s1 * (bih2[r1] + bhh2[r1]), 0.f);

    // x[e,t,:]: 7 packed pairs per step; depth-2 double buffer
    const ull* px = reinterpret_cast<const ull*>(x) + (size_t)ec * (TSEQ * INF / 2);
    ull xb[2][7];
#pragma unroll
    for (int k = 0; k < 7; k++) xb[0][k] = px[k];
#pragma unroll
    for (int k = 0; k < 7; k++) xb[1][k] = px[7 + k];
    px += 14;

    // broadcast pairs of previous h per layer
    ull Qh1[4] = {0,0,0,0}, Qh2[4] = {0,0,0,0};
    float c1 = 0.f, c2 = 0.f, h1o = 0.f, h2o = 0.f;

#pragma unroll 2
    for (int t = 0; t < TSEQ; t++){
        ull* cur = xb[t & 1];

        // ================= layer 1 =================
        ull a0 = pb10, a1 = pb11;
#pragma unroll
        for (int k = 0; k < 7; k++){
            a0 = ffma2(wx0[k], cur[k], a0);
            a1 = ffma2(wx1[k], cur[k], a1);
        }
        // cur free: prefetch x(t+2)
        if (t + 2 < TSEQ){
#pragma unroll
            for (int k = 0; k < 7; k++) cur[k] = px[k];
            px += 7;
        }
#pragma unroll
        for (int k = 0; k < 4; k++){
            a0 = ffma2(wh10[k], Qh1[k], a0);
            a1 = ffma2(wh11[k], Qh1[k], a1);
        }
        {
            const float2 u0 = upk(a0), u1 = upk(a1);
            const float A0 = fmaf(ca, tanhx(u0.x + u0.y), cb);   // sig(i) | tanh(g)
            const float A1 = fmaf(0.5f, tanhx(u1.x + u1.y), 0.5f); // sig(f) | sig(o)
            const float R0 = __shfl_xor_sync(FULL, A0, 8);       // tanh(g) | sig(i)
            const float R1 = __shfl_xor_sync(FULL, A1, 8);       // sig(o)  | sig(f)
            const float F = isP1 ? R1 : A1;                      // sig(f)
            const float O = isP1 ? A1 : R1;                      // sig(o)
            c1  = fmaf(F, c1, A0 * R0);                          // ig = A0*R0 both halves
            h1o = O * tanhx(c1);
        }
        // broadcast h1(t) pairs from own half (serves L2 now + L1 next step)
#pragma unroll
        for (int k = 0; k < 4; k++){
            Qh1[k] = pk(__shfl_sync(FULL, h1o, ob + 2*k),
                        __shfl_sync(FULL, h1o, ob + 2*k + 1));
        }

        // ================= layer 2 =================
        ull b0 = pb20, b1v = pb21;
#pragma unroll
        for (int k = 0; k < 4; k++){
            b0  = ffma2(wh20[k], Qh2[k], b0);
            b1v = ffma2(wh21[k], Qh2[k], b1v);
        }
#pragma unroll
        for (int k = 0; k < 4; k++){
            b0  = ffma2(wi20[k], Qh1[k], b0);
            b1v = ffma2(wi21[k], Qh1[k], b1v);
        }
        {
            const float2 u0 = upk(b0), u1 = upk(b1v);
            const float A0 = fmaf(ca, tanhx(u0.x + u0.y), cb);
            const float A1 = fmaf(0.5f, tanhx(u1.x + u1.y), 0.5f);
            const float R0 = __shfl_xor_sync(FULL, A0, 8);
            const float R1 = __shfl_xor_sync(FULL, A1, 8);
            const float F = isP1 ? R1 : A1;
            const float O = isP1 ? A1 : R1;
            c2  = fmaf(F, c2, A0 * R0);
            h2o = O * tanhx(c2);
        }
        // broadcast h2(t) pairs for next step's L2 h2-dot
#pragma unroll
        for (int k = 0; k < 4; k++){
            Qh2[k] = pk(__shfl_sync(FULL, h2o, ob + 2*k),
                        __shfl_sync(FULL, h2o, ob + 2*k + 1));
        }
    }

    // ---------------- epilogue: BatchNorm (eval) + MLP head ----------------
    // h2o = h2(T-1)[j], redundantly in both halves
    const float scale = bn_gamma[j] * rsqrtf(bn_var[j] + 1e-5f);
    const float nrm   = fmaf(h2o - bn_mean[j], scale, bn_beta[j]);

    float p0 = w1[0 * 8 + j] * nrm;
    float p1 = w1[1 * 8 + j] * nrm;
    float p2 = w1[2 * 8 + j] * nrm;
    float p3 = w1[3 * 8 + j] * nrm;
#pragma unroll
    for (int off = 4; off > 0; off >>= 1){   // reduce within aligned 8-lane groups
        p0 += __shfl_xor_sync(FULL, p0, off);
        p1 += __shfl_xor_sync(FULL, p1, off);
        p2 += __shfl_xor_sync(FULL, p2, off);
        p3 += __shfl_xor_sync(FULL, p3, off);
    }
    if (valid && (lane & 15) == 0){
        float o = b2[0];
        o = fmaf(w2[0], fmaxf(p0 + b1[0], 0.f), o);
        o = fmaf(w2[1], fmaxf(p1 + b1[1], 0.f), o);
        o = fmaf(w2[2], fmaxf(p2 + b1[2], 0.f), o);
        o = fmaf(w2[3], fmaxf(p3 + b1[3], 0.f), o);
        out[e] = o;
    }
}

extern "C" void kernel_launch(void* const* d_in, const int* in_sizes, int n_in,
                              void* d_out, int out_size)
{
    const float* x        = (const float*)d_in[0];
    const float* Wih1     = (const float*)d_in[1];
    const float* Whh1     = (const float*)d_in[2];
    const float* bih1     = (const float*)d_in[3];
    const float* bhh1     = (const float*)d_in[4];
    const float* Wih2     = (const float*)d_in[5];
    const float* Whh2     = (const float*)d_in[6];
    const float* bih2     = (const float*)d_in[7];
    const float* bhh2     = (const float*)d_in[8];
    const float* bn_gamma = (const float*)d_in[9];
    const float* bn_beta  = (const float*)d_in[10];
    const float* bn_mean  = (const float*)d_in[11];
    const float* bn_var   = (const float*)d_in[12];
    const float* w1       = (const float*)d_in[13];
    const float* b1       = (const float*)d_in[14];
    const float* w2       = (const float*)d_in[15];
    const float* b2       = (const float*)d_in[16];

    const int Bn = in_sizes[0] / (TSEQ * INF);
    const int grid = (Bn + 1) / 2;            // 2 batch elements per warp

    lstm_forex_kernel<<<grid, 32>>>(x, Wih1, Whh1, bih1, bhh1,
                                    Wih2, Whh2, bih2, bhh2,
                                    bn_gamma, bn_beta, bn_mean, bn_var,
                                    w1, b1, w2, b2,
                                    (float*)d_out, Bn);
}

// round 15
// speedup vs baseline: 1.5792x; 1.5792x over previous
#include <cuda_runtime.h>

#define TSEQ 512
#define INF  14

typedef unsigned long long ull;

__device__ __forceinline__ ull pk(float lo, float hi){
    ull r; asm("mov.b64 %0, {%1,%2};" : "=l"(r) : "f"(lo), "f"(hi)); return r;
}
__device__ __forceinline__ float2 upk(ull v){
    float2 r; asm("mov.b64 {%0,%1}, %2;" : "=f"(r.x), "=f"(r.y) : "l"(v)); return r;
}
__device__ __forceinline__ ull ffma2(ull a, ull b, ull c){
    ull d; asm("fma.rn.f32x2 %0, %1, %2, %3;" : "=l"(d) : "l"(a), "l"(b), "l"(c)); return d;
}
__device__ __forceinline__ ull fadd2(ull a, ull b){
    ull d; asm("add.rn.f32x2 %0, %1, %2;" : "=l"(d) : "l"(a), "l"(b)); return d;
}
__device__ __forceinline__ float tanhx(float x){
    float r; asm("tanh.approx.f32 %0, %1;" : "=f"(r) : "f"(x)); return r;
}
__device__ __forceinline__ float sigx(float x){
    return fmaf(0.5f, tanhx(0.5f * x), 0.5f);
}

// 4 batch elements per warp (8 lanes each); lane owns h-index j, all 4 gate rows.
// R9 champion + chain splitting: each L1 gate dot runs as TWO parallel
// accumulator chains (x-chain, h-chain) merged with one packed add, cutting
// the on-chain FFMA2 depth from 11 to ~8. Depth-2 x prefetch unchanged.
__global__ __launch_bounds__(32) void lstm_forex_kernel(
    const float* __restrict__ x,
    const float* __restrict__ Wih1, const float* __restrict__ Whh1,
    const float* __restrict__ bih1, const float* __restrict__ bhh1,
    const float* __restrict__ Wih2, const float* __restrict__ Whh2,
    const float* __restrict__ bih2, const float* __restrict__ bhh2,
    const float* __restrict__ bn_gamma, const float* __restrict__ bn_beta,
    const float* __restrict__ bn_mean, const float* __restrict__ bn_var,
    const float* __restrict__ w1, const float* __restrict__ b1,
    const float* __restrict__ w2, const float* __restrict__ b2,
    float* __restrict__ out, int Bn)
{
    const int lane = threadIdx.x & 31;
    const int j    = lane & 7;
    const int base = lane & 24;
    const int e    = blockIdx.x * 4 + (lane >> 3);
    const bool valid = (e < Bn);
    const int ec = valid ? e : (Bn > 0 ? Bn - 1 : 0);
    const unsigned FULL = 0xffffffffu;

    // ---- packed per-lane weights (gate rows j, j+8, j+16, j+24) ----
    ull wxp[4][7];    // (Wih1[row][2k], Wih1[row][2k+1])
    ull wh1p[4][4];   // Whh1 pairs
    ull wi2p[4][4];   // Wih2 pairs
    ull wh2p[4][4];   // Whh2 pairs
    ull pb1[4], pb2[4];
#pragma unroll
    for (int g = 0; g < 4; g++){
        const int row = g * 8 + j;
#pragma unroll
        for (int k = 0; k < 7; k++)
            wxp[g][k] = pk(Wih1[row * 14 + 2*k], Wih1[row * 14 + 2*k + 1]);
#pragma unroll
        for (int k = 0; k < 4; k++){
            wh1p[g][k] = pk(Whh1[row * 8 + 2*k], Whh1[row * 8 + 2*k + 1]);
            wi2p[g][k] = pk(Wih2[row * 8 + 2*k], Wih2[row * 8 + 2*k + 1]);
            wh2p[g][k] = pk(Whh2[row * 8 + 2*k], Whh2[row * 8 + 2*k + 1]);
        }
        pb1[g] = pk(bih1[row] + bhh1[row], 0.f);
        pb2[g] = pk(bih2[row] + bhh2[row], 0.f);
    }

    // x[e, t, :]: 14 floats = 7 packed pairs; depth-2 double buffer
    const ull* px = reinterpret_cast<const ull*>(x) + (size_t)ec * (TSEQ * INF / 2);
    ull xb[2][7];
#pragma unroll
    for (int k = 0; k < 7; k++) xb[0][k] = px[k];        // x(0)
#pragma unroll
    for (int k = 0; k < 7; k++) xb[1][k] = px[7 + k];    // x(1)
    px += 14;                                            // -> x(2)

    // packed broadcast state: h1p[k] = (h1[2k], h1[2k+1]); same for h2p
    ull h1p[4] = {0ull,0ull,0ull,0ull};
    ull h2p[4] = {0ull,0ull,0ull,0ull};
    float c1 = 0.f, c2 = 0.f, h2 = 0.f;

#pragma unroll 2
    for (int t = 0; t < TSEQ; t++){
        ull* cur = xb[t & 1];

        // ---- L1 x-dot: independent chain per gate (depth 7) ----
        ull xB0 = ffma2(wxp[0][0], cur[0], 0ull);
        ull xB1 = ffma2(wxp[1][0], cur[0], 0ull);
        ull xB2 = ffma2(wxp[2][0], cur[0], 0ull);
        ull xB3 = ffma2(wxp[3][0], cur[0], 0ull);
#pragma unroll
        for (int k = 1; k < 7; k++){
            xB0 = ffma2(wxp[0][k], cur[k], xB0);
            xB1 = ffma2(wxp[1][k], cur[k], xB1);
            xB2 = ffma2(wxp[2][k], cur[k], xB2);
            xB3 = ffma2(wxp[3][k], cur[k], xB3);
        }
        // cur is free: issue LDG for x(t+2) (~2 steps of latency cover)
        if (t + 2 < TSEQ){
#pragma unroll
            for (int k = 0; k < 7; k++) cur[k] = px[k];
            px += 7;
        }

        // ---- L2 partial: bias + Whh2*h2(t-1)  (independent of L1 chain) ----
        ull aA0 = pb2[0], aA1 = pb2[1], aA2 = pb2[2], aA3 = pb2[3];
#pragma unroll
        for (int k = 0; k < 4; k++){
            aA0 = ffma2(wh2p[0][k], h2p[k], aA0);
            aA1 = ffma2(wh2p[1][k], h2p[k], aA1);
            aA2 = ffma2(wh2p[2][k], h2p[k], aA2);
            aA3 = ffma2(wh2p[3][k], h2p[k], aA3);
        }

        // ---- L1 h-dot: PARALLEL chain (depth 4, starts from bias) ----
        ull aB0 = pb1[0], aB1 = pb1[1], aB2 = pb1[2], aB3 = pb1[3];
#pragma unroll
        for (int k = 0; k < 4; k++){
            aB0 = ffma2(wh1p[0][k], h1p[k], aB0);
            aB1 = ffma2(wh1p[1][k], h1p[k], aB1);
            aB2 = ffma2(wh1p[2][k], h1p[k], aB2);
            aB3 = ffma2(wh1p[3][k], h1p[k], aB3);
        }
        // merge the two chains (1 packed add each)
        aB0 = fadd2(aB0, xB0);
        aB1 = fadd2(aB1, xB1);
        aB2 = fadd2(aB2, xB2);
        aB3 = fadd2(aB3, xB3);

        // ---- L1 activations -> h1(t) ----
        float h1;
        {
            const float2 u0 = upk(aB0), u1 = upk(aB1), u2 = upk(aB2), u3 = upk(aB3);
            const float ai = sigx(u0.x + u0.y);
            const float af = sigx(u1.x + u1.y);
            const float ag = tanhx(u2.x + u2.y);
            const float ao = sigx(u3.x + u3.y);
            c1 = fmaf(af, c1, ai * ag);
            h1 = ao * tanhx(c1);
        }
        // ---- shuffle h1 ONCE; pairs feed L2(t) now and L1(t+1) next iter ----
#pragma unroll
        for (int k = 0; k < 4; k++){
            const float ha = __shfl_sync(FULL, h1, base + 2*k);
            const float hb = __shfl_sync(FULL, h1, base + 2*k + 1);
            h1p[k] = pk(ha, hb);
        }
        // ---- L2: + Wih2*h1(t), activations -> h2(t) ----
#pragma unroll
        for (int k = 0; k < 4; k++){
            aA0 = ffma2(wi2p[0][k], h1p[k], aA0);
            aA1 = ffma2(wi2p[1][k], h1p[k], aA1);
            aA2 = ffma2(wi2p[2][k], h1p[k], aA2);
            aA3 = ffma2(wi2p[3][k], h1p[k], aA3);
        }
        {
            const float2 u0 = upk(aA0), u1 = upk(aA1), u2 = upk(aA2), u3 = upk(aA3);
            const float ai = sigx(u0.x + u0.y);
            const float af = sigx(u1.x + u1.y);
            const float ag = tanhx(u2.x + u2.y);
            const float ao = sigx(u3.x + u3.y);
            c2 = fmaf(af, c2, ai * ag);
            h2 = ao * tanhx(c2);
        }
        // ---- shuffle h2 ONCE; pairs feed next iteration's L2 partial ----
#pragma unroll
        for (int k = 0; k < 4; k++){
            const float ha = __shfl_sync(FULL, h2, base + 2*k);
            const float hb = __shfl_sync(FULL, h2, base + 2*k + 1);
            h2p[k] = pk(ha, hb);
        }
    }

    // ---------------- epilogue: BatchNorm (eval) + MLP head ----------------
    const float scale = bn_gamma[j] * rsqrtf(bn_var[j] + 1e-5f);
    const float nrm   = fmaf(h2 - bn_mean[j], scale, bn_beta[j]);

    float p0 = w1[0 * 8 + j] * nrm;
    float p1 = w1[1 * 8 + j] * nrm;
    float p2 = w1[2 * 8 + j] * nrm;
    float p3 = w1[3 * 8 + j] * nrm;
#pragma unroll
    for (int off = 4; off > 0; off >>= 1){
        p0 += __shfl_xor_sync(FULL, p0, off);
        p1 += __shfl_xor_sync(FULL, p1, off);
        p2 += __shfl_xor_sync(FULL, p2, off);
        p3 += __shfl_xor_sync(FULL, p3, off);
    }
    if (valid && j == 0){
        float o = b2[0];
        o = fmaf(w2[0], fmaxf(p0 + b1[0], 0.f), o);
        o = fmaf(w2[1], fmaxf(p1 + b1[1], 0.f), o);
        o = fmaf(w2[2], fmaxf(p2 + b1[2], 0.f), o);
        o = fmaf(w2[3], fmaxf(p3 + b1[3], 0.f), o);
        out[e] = o;
    }
}

extern "C" void kernel_launch(void* const* d_in, const int* in_sizes, int n_in,
                              void* d_out, int out_size)
{
    const float* x        = (const float*)d_in[0];
    const float* Wih1     = (const float*)d_in[1];
    const float* Whh1     = (const float*)d_in[2];
    const float* bih1     = (const float*)d_in[3];
    const float* bhh1     = (const float*)d_in[4];
    const float* Wih2     = (const float*)d_in[5];
    const float* Whh2     = (const float*)d_in[6];
    const float* bih2     = (const float*)d_in[7];
    const float* bhh2     = (const float*)d_in[8];
    const float* bn_gamma = (const float*)d_in[9];
    const float* bn_beta  = (const float*)d_in[10];
    const float* bn_mean  = (const float*)d_in[11];
    const float* bn_var   = (const float*)d_in[12];
    const float* w1       = (const float*)d_in[13];
    const float* b1       = (const float*)d_in[14];
    const float* w2       = (const float*)d_in[15];
    const float* b2       = (const float*)d_in[16];

    const int Bn = in_sizes[0] / (TSEQ * INF);
    const int grid = (Bn + 3) / 4;            // 4 batch elements per warp, 1 warp/block

    lstm_forex_kernel<<<grid, 32>>>(x, Wih1, Whh1, bih1, bhh1,
                                    Wih2, Whh2, bih2, bhh2,
                                    bn_gamma, bn_beta, bn_mean, bn_var,
                                    w1, b1, w2, b2,
                                    (float*)d_out, Bn);
}

// round 16
// speedup vs baseline: 1.6154x; 1.0229x over previous
#include <cuda_runtime.h>

#define TSEQ 512
#define INF  14

typedef unsigned long long ull;

__device__ __forceinline__ ull pk(float lo, float hi){
    ull r; asm("mov.b64 %0, {%1,%2};" : "=l"(r) : "f"(lo), "f"(hi)); return r;
}
__device__ __forceinline__ float2 upk(ull v){
    float2 r; asm("mov.b64 {%0,%1}, %2;" : "=f"(r.x), "=f"(r.y) : "l"(v)); return r;
}
__device__ __forceinline__ ull ffma2(ull a, ull b, ull c){
    ull d; asm("fma.rn.f32x2 %0, %1, %2, %3;" : "=l"(d) : "l"(a), "l"(b), "l"(c)); return d;
}
__device__ __forceinline__ ull fadd2(ull a, ull b){
    ull d; asm("add.rn.f32x2 %0, %1, %2;" : "=l"(d) : "l"(a), "l"(b)); return d;
}
__device__ __forceinline__ float tanhx(float x){
    float r; asm("tanh.approx.f32 %0, %1;" : "=f"(r) : "f"(x)); return r;
}
// gate weights for i/f/o pre-scaled by 0.5 => sigmoid(orig) = 0.5*tanh(s)+0.5
__device__ __forceinline__ float sig_ps(float s){
    return fmaf(0.5f, tanhx(s), 0.5f);
}

// 4 batch elements per warp (8 lanes each); lane owns h-index j, all 4 gate rows.
// R15 champion (chain-split L1 dot, shuffle-once, depth-2 x prefetch) plus:
//  - i/f/o gate rows pre-scaled by 0.5 (kills 6 FMUL/step)
//  - L2 h2-partial dot moved to loop top (operands ready longest -> fills the
//    shuffle-latency shadow from the previous iteration)
__global__ __launch_bounds__(32) void lstm_forex_kernel(
    const float* __restrict__ x,
    const float* __restrict__ Wih1, const float* __restrict__ Whh1,
    const float* __restrict__ bih1, const float* __restrict__ bhh1,
    const float* __restrict__ Wih2, const float* __restrict__ Whh2,
    const float* __restrict__ bih2, const float* __restrict__ bhh2,
    const float* __restrict__ bn_gamma, const float* __restrict__ bn_beta,
    const float* __restrict__ bn_mean, const float* __restrict__ bn_var,
    const float* __restrict__ w1, const float* __restrict__ b1,
    const float* __restrict__ w2, const float* __restrict__ b2,
    float* __restrict__ out, int Bn)
{
    const int lane = threadIdx.x & 31;
    const int j    = lane & 7;
    const int base = lane & 24;
    const int e    = blockIdx.x * 4 + (lane >> 3);
    const bool valid = (e < Bn);
    const int ec = valid ? e : (Bn > 0 ? Bn - 1 : 0);
    const unsigned FULL = 0xffffffffu;

    // gate scales: i,f,o pre-scaled by 0.5 (sigmoid via tanh); g unscaled
    const float gsc[4] = {0.5f, 0.5f, 1.0f, 0.5f};

    // ---- packed per-lane weights (gate rows j, j+8, j+16, j+24) ----
    ull wxp[4][7];    // Wih1 pairs * gsc
    ull wh1p[4][4];   // Whh1 pairs * gsc
    ull wi2p[4][4];   // Wih2 pairs * gsc
    ull wh2p[4][4];   // Whh2 pairs * gsc
    ull pb1[4], pb2[4];
#pragma unroll
    for (int g = 0; g < 4; g++){
        const int row = g * 8 + j;
        const float s = gsc[g];
#pragma unroll
        for (int k = 0; k < 7; k++)
            wxp[g][k] = pk(s * Wih1[row * 14 + 2*k], s * Wih1[row * 14 + 2*k + 1]);
#pragma unroll
        for (int k = 0; k < 4; k++){
            wh1p[g][k] = pk(s * Whh1[row * 8 + 2*k], s * Whh1[row * 8 + 2*k + 1]);
            wi2p[g][k] = pk(s * Wih2[row * 8 + 2*k], s * Wih2[row * 8 + 2*k + 1]);
            wh2p[g][k] = pk(s * Whh2[row * 8 + 2*k], s * Whh2[row * 8 + 2*k + 1]);
        }
        pb1[g] = pk(s * (bih1[row] + bhh1[row]), 0.f);
        pb2[g] = pk(s * (bih2[row] + bhh2[row]), 0.f);
    }

    // x[e, t, :]: 14 floats = 7 packed pairs; depth-2 double buffer
    const ull* px = reinterpret_cast<const ull*>(x) + (size_t)ec * (TSEQ * INF / 2);
    ull xb[2][7];
#pragma unroll
    for (int k = 0; k < 7; k++) xb[0][k] = px[k];        // x(0)
#pragma unroll
    for (int k = 0; k < 7; k++) xb[1][k] = px[7 + k];    // x(1)
    px += 14;                                            // -> x(2)

    // packed broadcast state: h1p[k] = (h1[2k], h1[2k+1]); same for h2p
    ull h1p[4] = {0ull,0ull,0ull,0ull};
    ull h2p[4] = {0ull,0ull,0ull,0ull};
    float c1 = 0.f, c2 = 0.f, h2 = 0.f;

#pragma unroll 2
    for (int t = 0; t < TSEQ; t++){
        ull* cur = xb[t & 1];

        // ---- L2 partial FIRST: bias + Whh2*h2(t-1) (operands ready longest;
        //      fills the shuffle shadow from last iteration) ----
        ull aA0 = pb2[0], aA1 = pb2[1], aA2 = pb2[2], aA3 = pb2[3];
#pragma unroll
        for (int k = 0; k < 4; k++){
            aA0 = ffma2(wh2p[0][k], h2p[k], aA0);
            aA1 = ffma2(wh2p[1][k], h2p[k], aA1);
            aA2 = ffma2(wh2p[2][k], h2p[k], aA2);
            aA3 = ffma2(wh2p[3][k], h2p[k], aA3);
        }

        // ---- L1 x-dot: independent chain per gate (depth 7) ----
        ull xB0 = ffma2(wxp[0][0], cur[0], 0ull);
        ull xB1 = ffma2(wxp[1][0], cur[0], 0ull);
        ull xB2 = ffma2(wxp[2][0], cur[0], 0ull);
        ull xB3 = ffma2(wxp[3][0], cur[0], 0ull);
#pragma unroll
        for (int k = 1; k < 7; k++){
            xB0 = ffma2(wxp[0][k], cur[k], xB0);
            xB1 = ffma2(wxp[1][k], cur[k], xB1);
            xB2 = ffma2(wxp[2][k], cur[k], xB2);
            xB3 = ffma2(wxp[3][k], cur[k], xB3);
        }
        // cur is free: issue LDG for x(t+2) (~2 steps of latency cover)
        if (t + 2 < TSEQ){
#pragma unroll
            for (int k = 0; k < 7; k++) cur[k] = px[k];
            px += 7;
        }

        // ---- L1 h-dot: PARALLEL chain (depth 4, starts from bias) ----
        ull aB0 = pb1[0], aB1 = pb1[1], aB2 = pb1[2], aB3 = pb1[3];
#pragma unroll
        for (int k = 0; k < 4; k++){
            aB0 = ffma2(wh1p[0][k], h1p[k], aB0);
            aB1 = ffma2(wh1p[1][k], h1p[k], aB1);
            aB2 = ffma2(wh1p[2][k], h1p[k], aB2);
            aB3 = ffma2(wh1p[3][k], h1p[k], aB3);
        }
        // merge chains (1 packed add each)
        aB0 = fadd2(aB0, xB0);
        aB1 = fadd2(aB1, xB1);
        aB2 = fadd2(aB2, xB2);
        aB3 = fadd2(aB3, xB3);

        // ---- L1 activations -> h1(t) ----
        float h1;
        {
            const float2 u0 = upk(aB0), u1 = upk(aB1), u2 = upk(aB2), u3 = upk(aB3);
            const float ai = sig_ps(u0.x + u0.y);
            const float af = sig_ps(u1.x + u1.y);
            const float ag = tanhx(u2.x + u2.y);
            const float ao = sig_ps(u3.x + u3.y);
            c1 = fmaf(af, c1, ai * ag);
            h1 = ao * tanhx(c1);
        }
        // ---- shuffle h1 ONCE; pairs feed L2(t) now and L1(t+1) next iter ----
#pragma unroll
        for (int k = 0; k < 4; k++){
            const float ha = __shfl_sync(FULL, h1, base + 2*k);
            const float hb = __shfl_sync(FULL, h1, base + 2*k + 1);
            h1p[k] = pk(ha, hb);
        }
        // ---- L2: + Wih2*h1(t), activations -> h2(t) ----
#pragma unroll
        for (int k = 0; k < 4; k++){
            aA0 = ffma2(wi2p[0][k], h1p[k], aA0);
            aA1 = ffma2(wi2p[1][k], h1p[k], aA1);
            aA2 = ffma2(wi2p[2][k], h1p[k], aA2);
            aA3 = ffma2(wi2p[3][k], h1p[k], aA3);
        }
        {
            const float2 u0 = upk(aA0), u1 = upk(aA1), u2 = upk(aA2), u3 = upk(aA3);
            const float ai = sig_ps(u0.x + u0.y);
            const float af = sig_ps(u1.x + u1.y);
            const float ag = tanhx(u2.x + u2.y);
            const float ao = sig_ps(u3.x + u3.y);
            c2 = fmaf(af, c2, ai * ag);
            h2 = ao * tanhx(c2);
        }
        // ---- shuffle h2 ONCE; pairs feed next iteration's L2 partial ----
#pragma unroll
        for (int k = 0; k < 4; k++){
            const float ha = __shfl_sync(FULL, h2, base + 2*k);
            const float hb = __shfl_sync(FULL, h2, base + 2*k + 1);
            h2p[k] = pk(ha, hb);
        }
    }

    // ---------------- epilogue: BatchNorm (eval) + MLP head ----------------
    const float scale = bn_gamma[j] * rsqrtf(bn_var[j] + 1e-5f);
    const float nrm   = fmaf(h2 - bn_mean[j], scale, bn_beta[j]);

    float p0 = w1[0 * 8 + j] * nrm;
    float p1 = w1[1 * 8 + j] * nrm;
    float p2 = w1[2 * 8 + j] * nrm;
    float p3 = w1[3 * 8 + j] * nrm;
#pragma unroll
    for (int off = 4; off > 0; off >>= 1){
        p0 += __shfl_xor_sync(FULL, p0, off);
        p1 += __shfl_xor_sync(FULL, p1, off);
        p2 += __shfl_xor_sync(FULL, p2, off);
        p3 += __shfl_xor_sync(FULL, p3, off);
    }
    if (valid && j == 0){
        float o = b2[0];
        o = fmaf(w2[0], fmaxf(p0 + b1[0], 0.f), o);
        o = fmaf(w2[1], fmaxf(p1 + b1[1], 0.f), o);
        o = fmaf(w2[2], fmaxf(p2 + b1[2], 0.f), o);
        o = fmaf(w2[3], fmaxf(p3 + b1[3], 0.f), o);
        out[e] = o;
    }
}

extern "C" void kernel_launch(void* const* d_in, const int* in_sizes, int n_in,
                              void* d_out, int out_size)
{
    const float* x        = (const float*)d_in[0];
    const float* Wih1     = (const float*)d_in[1];
    const float* Whh1     = (const float*)d_in[2];
    const float* bih1     = (const float*)d_in[3];
    const float* bhh1     = (const float*)d_in[4];
    const float* Wih2     = (const float*)d_in[5];
    const float* Whh2     = (const float*)d_in[6];
    const float* bih2     = (const float*)d_in[7];
    const float* bhh2     = (const float*)d_in[8];
    const float* bn_gamma = (const float*)d_in[9];
    const float* bn_beta  = (const float*)d_in[10];
    const float* bn_mean  = (const float*)d_in[11];
    const float* bn_var   = (const float*)d_in[12];
    const float* w1       = (const float*)d_in[13];
    const float* b1       = (const float*)d_in[14];
    const float* w2       = (const float*)d_in[15];
    const float* b2       = (const float*)d_in[16];

    const int Bn = in_sizes[0] / (TSEQ * INF);
    const int grid = (Bn + 3) / 4;            // 4 batch elements per warp, 1 warp/block

    lstm_forex_kernel<<<grid, 32>>>(x, Wih1, Whh1, bih1, bhh1,
                                    Wih2, Whh2, bih2, bhh2,
                                    bn_gamma, bn_beta, bn_mean, bn_var,
                                    w1, b1, w2, b2,
                                    (float*)d_out, Bn);
}